// round 4
// baseline (speedup 1.0000x reference)
#include <cuda_runtime.h>
#include <math.h>

#define NN 51200      // nodes
#define EE 409600     // edges (without self loops)
#define BB 256        // batch
#define NHOST 13
#define IN_F 64
#define H1 256
#define H2 64
#define ZN 65536      // max(NN, BB*H1) — elements to zero

typedef unsigned long long u64;

// ---------------- scratch (static device globals; no runtime alloc) -------
__device__ int   d_cnt[NN];
__device__ int   d_off[NN + 1];
__device__ int   d_cur[NN];
__device__ int   d_csr[EE];
__device__ int   d_flag[NN];    // frontier: hosts ∪ in-neighbors of hosts
__device__ int   d_ishost[NN];
__device__ float d_dinv[NN];
__device__ float d_xw[(size_t)NN * H1];    // dinv * (x @ W1)
__device__ float d_x1[(size_t)NN * H1];    // relu(agg1 + b1), frontier rows only (rest stay 0)
__device__ float d_xw2[(size_t)NN * H2];   // dinv * (x1 @ W2)
__device__ float d_x2h[(size_t)BB * NHOST * H2];
__device__ float d_g[(size_t)BB * H1];     // global state

// ---------------- zero ------------------------------------------------------
__global__ void k_zero() {
    int i = blockIdx.x * blockDim.x + threadIdx.x;
    if (i < NN) { d_cnt[i] = 0; d_flag[i] = 0; d_ishost[i] = 0; }
    if (i < BB * H1) d_g[i] = 0.f;
}

// count in-degree; also mark host nodes
__global__ void k_count_mh(const int* __restrict__ dst, const int* __restrict__ hidx) {
    int e = blockIdx.x * blockDim.x + threadIdx.x;
    if (e < EE) atomicAdd(&d_cnt[dst[e]], 1);
    if (e < BB * NHOST) {
        int n = hidx[e];
        d_ishost[n] = 1;
        d_flag[n] = 1;
    }
}

// 1 block, 1024 threads, 50 items each (51200 = 1024*50)
__global__ void k_scan() {
    __shared__ int part[1024];
    int t = threadIdx.x;
    int base = t * 50;
    int s = 0;
    for (int i = 0; i < 50; i++) s += d_cnt[base + i];
    part[t] = s;
    __syncthreads();
    for (int d = 1; d < 1024; d <<= 1) {
        int v = part[t];
        int add = (t >= d) ? part[t - d] : 0;
        __syncthreads();
        part[t] = v + add;
        __syncthreads();
    }
    int run = part[t] - s;  // exclusive prefix
    for (int i = 0; i < 50; i++) {
        int c = d_cnt[base + i];
        d_off[base + i] = run;
        d_cur[base + i] = run;
        d_dinv[base + i] = rsqrtf((float)(c + 1));  // +1 self loop
        run += c;
    }
    if (t == 1023) d_off[NN] = run;
}

// fill CSR; also mark in-neighbors of hosts (frontier)
__global__ void k_fill_me(const int* __restrict__ src, const int* __restrict__ dst) {
    int e = blockIdx.x * blockDim.x + threadIdx.x;
    if (e < EE) {
        int d = dst[e];
        int s = src[e];
        int p = atomicAdd(&d_cur[d], 1);
        d_csr[p] = s;
        if (d_ishost[d]) d_flag[s] = 1;
    }
}

// ---------------- GEMM1: xw = dinv * (x @ W1)  [51200,64]x[64,256] ---------
#define G1R 32
__global__ void k_gemm1(const float* __restrict__ x, const float* __restrict__ W1) {
    __shared__ float xs[IN_F][G1R + 2];
    int r0 = blockIdx.x * G1R;
    int t = threadIdx.x; // 256
    for (int i = t; i < G1R * IN_F; i += 256) {
        int r = i >> 6, k = i & 63;
        xs[k][r] = x[(size_t)(r0 + r) * IN_F + k];
    }
    __syncthreads();
    u64 acc[G1R / 2];
#pragma unroll
    for (int p = 0; p < G1R / 2; p++) acc[p] = 0ull;
    for (int k = 0; k < IN_F; k++) {
        float w = __ldg(&W1[k * H1 + t]);
        u64 ww;
        asm("mov.b64 %0, {%1, %1};" : "=l"(ww) : "f"(w));
#pragma unroll
        for (int p = 0; p < G1R / 2; p++) {
            u64 xv = *reinterpret_cast<const u64*>(&xs[k][2 * p]);
            asm("fma.rn.f32x2 %0, %1, %2, %0;" : "+l"(acc[p]) : "l"(xv), "l"(ww));
        }
    }
#pragma unroll
    for (int p = 0; p < G1R / 2; p++) {
        float lo, hi;
        asm("mov.b64 {%0, %1}, %2;" : "=f"(lo), "=f"(hi) : "l"(acc[p]));
        d_xw[(size_t)(r0 + 2 * p) * H1 + t]     = d_dinv[r0 + 2 * p] * lo;
        d_xw[(size_t)(r0 + 2 * p + 1) * H1 + t] = d_dinv[r0 + 2 * p + 1] * hi;
    }
}

// ---------------- layer-1 max aggregation (frontier, grid-stride) ----------
#define AGG1_GRID 4096
__global__ void k_agg1(const float* __restrict__ b1) {
    int t = threadIdx.x; // 256
    float bias = __ldg(&b1[t]);
    for (int i = blockIdx.x; i < NN; i += AGG1_GRID) {
        if (d_flag[i] == 0) continue;   // non-frontier: x1 row stays 0 forever
        float m = d_xw[(size_t)i * H1 + t];   // self message (y = dinv*xw)
        int e0 = d_off[i], e1 = d_off[i + 1];
        int e = e0;
        for (; e + 4 <= e1; e += 4) {
            int s0 = __ldg(&d_csr[e]);
            int s1 = __ldg(&d_csr[e + 1]);
            int s2 = __ldg(&d_csr[e + 2]);
            int s3 = __ldg(&d_csr[e + 3]);
            float v0 = __ldg(&d_xw[(size_t)s0 * H1 + t]);
            float v1 = __ldg(&d_xw[(size_t)s1 * H1 + t]);
            float v2 = __ldg(&d_xw[(size_t)s2 * H1 + t]);
            float v3 = __ldg(&d_xw[(size_t)s3 * H1 + t]);
            m = fmaxf(m, fmaxf(fmaxf(v0, v1), fmaxf(v2, v3)));
        }
        for (; e < e1; e++)
            m = fmaxf(m, __ldg(&d_xw[(size_t)__ldg(&d_csr[e]) * H1 + t]));
        d_x1[(size_t)i * H1 + t] = fmaxf(d_dinv[i] * m + bias, 0.f);
    }
}

// ---------------- GEMM2: xw2 = dinv * (x1 @ W2)  [51200,256]x[256,64] ------
#define G2R 64
__global__ void k_gemm2(const float* __restrict__ W2) {
    __shared__ float xs[64][G2R + 2];
    int r0 = blockIdx.x * G2R;
    int t = threadIdx.x;      // 256
    int j = t & 63;
    int rg = t >> 6;
    u64 acc[8];
#pragma unroll
    for (int p = 0; p < 8; p++) acc[p] = 0ull;
    for (int kc = 0; kc < H1; kc += 64) {
        __syncthreads();
        for (int i = t; i < G2R * 64; i += 256) {
            int r = i >> 6, k = i & 63;
            xs[k][r] = d_x1[(size_t)(r0 + r) * H1 + kc + k];
        }
        __syncthreads();
        for (int k = 0; k < 64; k++) {
            float w = __ldg(&W2[(kc + k) * H2 + j]);
            u64 ww;
            asm("mov.b64 %0, {%1, %1};" : "=l"(ww) : "f"(w));
#pragma unroll
            for (int p = 0; p < 8; p++) {
                u64 xv = *reinterpret_cast<const u64*>(&xs[k][rg * 16 + 2 * p]);
                asm("fma.rn.f32x2 %0, %1, %2, %0;" : "+l"(acc[p]) : "l"(xv), "l"(ww));
            }
        }
    }
#pragma unroll
    for (int p = 0; p < 8; p++) {
        float lo, hi;
        asm("mov.b64 {%0, %1}, %2;" : "=f"(lo), "=f"(hi) : "l"(acc[p]));
        int ra = r0 + rg * 16 + 2 * p;
        d_xw2[(size_t)ra * H2 + j]       = d_dinv[ra] * lo;
        d_xw2[(size_t)(ra + 1) * H2 + j] = d_dinv[ra + 1] * hi;
    }
}

// ---------------- layer-2 max aggregation (HOST nodes only) ---------------
__global__ void k_agg2(const int* __restrict__ hidx, const float* __restrict__ b2) {
    int hi = blockIdx.x;       // 0..BB*NHOST-1
    int t = threadIdx.x;       // 64
    int node = __ldg(&hidx[hi]);
    float m = d_xw2[(size_t)node * H2 + t];
    int e0 = d_off[node], e1 = d_off[node + 1];
    int e = e0;
    for (; e + 4 <= e1; e += 4) {
        int s0 = __ldg(&d_csr[e]);
        int s1 = __ldg(&d_csr[e + 1]);
        int s2 = __ldg(&d_csr[e + 2]);
        int s3 = __ldg(&d_csr[e + 3]);
        float v0 = __ldg(&d_xw2[(size_t)s0 * H2 + t]);
        float v1 = __ldg(&d_xw2[(size_t)s1 * H2 + t]);
        float v2 = __ldg(&d_xw2[(size_t)s2 * H2 + t]);
        float v3 = __ldg(&d_xw2[(size_t)s3 * H2 + t]);
        m = fmaxf(m, fmaxf(fmaxf(v0, v1), fmaxf(v2, v3)));
    }
    for (; e < e1; e++)
        m = fmaxf(m, __ldg(&d_xw2[(size_t)__ldg(&d_csr[e]) * H2 + t]));
    d_x2h[(size_t)hi * H2 + t] = fmaxf(d_dinv[node] * m + __ldg(&b2[t]), 0.f);
}

// ---------------- self attention (templated on F,H; G=256) ----------------
template <int F, int H>
__global__ void k_attn(const float* __restrict__ v, const int* __restrict__ hidx,
                       const float* __restrict__ aW, const float* __restrict__ ab,
                       const float* __restrict__ fW, const float* __restrict__ fb,
                       const float* __restrict__ gW, const float* __restrict__ gb) {
    int b = blockIdx.x;
    int t = threadIdx.x; // 256
    __shared__ float vsT[F][16];       // f-major, 13 hosts padded to 16
    __shared__ float ls[NHOST * H];
    __shared__ float mx[NHOST], sm[NHOST];
    __shared__ float outs[H];
    __shared__ float gs[H1];

    for (int i = t; i < NHOST * F; i += 256) {
        int h = i / F, f = i % F;
        int row = hidx ? hidx[b * NHOST + h] : (b * NHOST + h);
        vsT[f][h] = v[(size_t)row * F + f];
    }
    gs[t] = d_g[(size_t)b * H1 + t];
    __syncthreads();

    float aL[NHOST], fV[NHOST];
    if (t < H) {
#pragma unroll
        for (int h = 0; h < NHOST; h++) { aL[h] = ab[t]; fV[h] = fb[t]; }
#pragma unroll 2
        for (int f = 0; f < F; f++) {
            float wa = __ldg(&aW[f * H + t]);
            float wf = __ldg(&fW[f * H + t]);
            float4 v0 = *reinterpret_cast<const float4*>(&vsT[f][0]);
            float4 v1 = *reinterpret_cast<const float4*>(&vsT[f][4]);
            float4 v2 = *reinterpret_cast<const float4*>(&vsT[f][8]);
            float vc = vsT[f][12];
            aL[0] += v0.x * wa;  fV[0] += v0.x * wf;
            aL[1] += v0.y * wa;  fV[1] += v0.y * wf;
            aL[2] += v0.z * wa;  fV[2] += v0.z * wf;
            aL[3] += v0.w * wa;  fV[3] += v0.w * wf;
            aL[4] += v1.x * wa;  fV[4] += v1.x * wf;
            aL[5] += v1.y * wa;  fV[5] += v1.y * wf;
            aL[6] += v1.z * wa;  fV[6] += v1.z * wf;
            aL[7] += v1.w * wa;  fV[7] += v1.w * wf;
            aL[8] += v2.x * wa;  fV[8] += v2.x * wf;
            aL[9] += v2.y * wa;  fV[9] += v2.y * wf;
            aL[10] += v2.z * wa; fV[10] += v2.z * wf;
            aL[11] += v2.w * wa; fV[11] += v2.w * wf;
            aL[12] += vc * wa;   fV[12] += vc * wf;
        }
#pragma unroll
        for (int h = 0; h < NHOST; h++) ls[h * H + t] = aL[h];
    }
    __syncthreads();
    if (t < NHOST) {
        float m = -1e30f;
        for (int j = 0; j < H; j++) m = fmaxf(m, ls[t * H + j]);
        mx[t] = m;
    }
    __syncthreads();
    if (t < H) {
#pragma unroll
        for (int h = 0; h < NHOST; h++) ls[h * H + t] = expf(aL[h] - mx[h]);
    }
    __syncthreads();
    if (t < NHOST) {
        float s = 0.f;
        for (int j = 0; j < H; j++) s += ls[t * H + j];
        sm[t] = s;
    }
    __syncthreads();
    if (t < H) {
        float o = 0.f;
#pragma unroll
        for (int h = 0; h < NHOST; h++) o += (ls[h * H + t] / sm[h]) * fV[h];
        outs[t] = o;
    }
    __syncthreads();

    // g_new = concat(out[H], g[256]) @ gW[(H+256),256] + gb ; g += g_new
    float a0 = gb[t], a1 = 0.f, a2 = 0.f, a3 = 0.f;
#pragma unroll 1
    for (int k = 0; k < H; k += 4) {
        a0 += outs[k]     * __ldg(&gW[(k)     * H1 + t]);
        a1 += outs[k + 1] * __ldg(&gW[(k + 1) * H1 + t]);
        a2 += outs[k + 2] * __ldg(&gW[(k + 2) * H1 + t]);
        a3 += outs[k + 3] * __ldg(&gW[(k + 3) * H1 + t]);
    }
#pragma unroll 1
    for (int k = 0; k < H1; k += 4) {
        a0 += gs[k]     * __ldg(&gW[(H + k)     * H1 + t]);
        a1 += gs[k + 1] * __ldg(&gW[(H + k + 1) * H1 + t]);
        a2 += gs[k + 2] * __ldg(&gW[(H + k + 2) * H1 + t]);
        a3 += gs[k + 3] * __ldg(&gW[(H + k + 3) * H1 + t]);
    }
    d_g[(size_t)b * H1 + t] = gs[t] + (a0 + a1) + (a2 + a3);
}

// ---------------- final head: relu(g@o1W+o1b)@o2W + o2b -------------------
__global__ void k_head(const float* __restrict__ o1W, const float* __restrict__ o1b,
                       const float* __restrict__ o2W, const float* __restrict__ o2b,
                       float* __restrict__ out) {
    int b = blockIdx.x;
    int t = threadIdx.x; // 64
    __shared__ float gs[H1];
    for (int i = t; i < H1; i += 64) gs[i] = d_g[(size_t)b * H1 + i];
    __syncthreads();
    float a0 = o1b[t], a1 = 0.f, a2 = 0.f, a3 = 0.f;
    for (int k = 0; k < H1; k += 4) {
        a0 += gs[k]     * __ldg(&o1W[(k)     * H2 + t]);
        a1 += gs[k + 1] * __ldg(&o1W[(k + 1) * H2 + t]);
        a2 += gs[k + 2] * __ldg(&o1W[(k + 2) * H2 + t]);
        a3 += gs[k + 3] * __ldg(&o1W[(k + 3) * H2 + t]);
    }
    float acc = (a0 + a1) + (a2 + a3);
    float v = fmaxf(acc, 0.f) * __ldg(&o2W[t]);
    __shared__ float rs[64];
    rs[t] = v;
    __syncthreads();
    if (t < 32) {
        float s = rs[t] + rs[t + 32];
#pragma unroll
        for (int d = 16; d > 0; d >>= 1) s += __shfl_down_sync(0xffffffffu, s, d);
        if (t == 0) out[b] = s + o2b[0];
    }
}

// ---------------- launch ---------------------------------------------------
extern "C" void kernel_launch(void* const* d_in, const int* in_sizes, int n_in,
                              void* d_out, int out_size) {
    const float* x       = (const float*)d_in[0];
    const int*   ei      = (const int*)d_in[1];   // [2,E] int32
    const int*   hostidx = (const int*)d_in[2];
    const float* W1 = (const float*)d_in[3];
    const float* b1 = (const float*)d_in[4];
    const float* W2 = (const float*)d_in[5];
    const float* b2 = (const float*)d_in[6];
    const float* a0W = (const float*)d_in[7];  const float* a0b = (const float*)d_in[8];
    const float* f0W = (const float*)d_in[9];  const float* f0b = (const float*)d_in[10];
    const float* g0W = (const float*)d_in[11]; const float* g0b = (const float*)d_in[12];
    const float* a1W = (const float*)d_in[13]; const float* a1b = (const float*)d_in[14];
    const float* f1W = (const float*)d_in[15]; const float* f1b = (const float*)d_in[16];
    const float* g1W = (const float*)d_in[17]; const float* g1b = (const float*)d_in[18];
    const float* a2W = (const float*)d_in[19]; const float* a2b = (const float*)d_in[20];
    const float* f2W = (const float*)d_in[21]; const float* f2b = (const float*)d_in[22];
    const float* g2W = (const float*)d_in[23]; const float* g2b = (const float*)d_in[24];
    const float* o1W = (const float*)d_in[25]; const float* o1b = (const float*)d_in[26];
    const float* o2W = (const float*)d_in[27]; const float* o2b = (const float*)d_in[28];
    float* out = (float*)d_out;

    const int* src = ei;
    const int* dst = ei + EE;

    float* x1_ptr;  cudaGetSymbolAddress((void**)&x1_ptr,  d_x1);
    float* x2h_ptr; cudaGetSymbolAddress((void**)&x2h_ptr, d_x2h);

    // graph build (launch order arranged so k_agg1 is the 6th launch → profiled)
    k_zero<<<ZN / 256, 256>>>();                               // 1
    k_count_mh<<<(EE + 255) / 256, 256>>>(dst, hostidx);       // 2
    k_scan<<<1, 1024>>>();                                     // 3
    k_fill_me<<<(EE + 255) / 256, 256>>>(src, dst);            // 4

    // layer 1
    k_gemm1<<<NN / G1R, 256>>>(x, W1);                         // 5
    k_agg1<<<AGG1_GRID, 256>>>(b1);                            // 6  ← ncu -s 5 -c 1
    // stage 0 attention (independent of graph build; only needs d_g=0)
    k_attn<IN_F, H1><<<BB, 256>>>(x, hostidx, a0W, a0b, f0W, f0b, g0W, g0b);   // 7
    k_attn<H1, H1><<<BB, 256>>>(x1_ptr, hostidx, a1W, a1b, f1W, f1b, g1W, g1b); // 8

    // layer 2 (aggregation on host nodes only)
    k_gemm2<<<NN / G2R, 256>>>(W2);                            // 9
    k_agg2<<<BB * NHOST, 64>>>(hostidx, b2);                   // 10
    k_attn<H2, H2><<<BB, 256>>>(x2h_ptr, (const int*)nullptr, a2W, a2b, f2W, f2b, g2W, g2b); // 11

    // head
    k_head<<<BB, 64>>>(o1W, o1b, o2W, o2b, out);               // 12
}

// round 5
// speedup vs baseline: 1.2625x; 1.2625x over previous
#include <cuda_runtime.h>
#include <math.h>

#define NN 51200      // nodes
#define EE 409600     // edges (without self loops)
#define BB 256        // batch
#define NHOST 13
#define IN_F 64
#define H1 256
#define H2 64
#define ZN 65536      // max(NN, BB*H1) — elements to zero

typedef unsigned long long u64;

// ---------------- scratch (static device globals; no runtime alloc) -------
__device__ int   d_cnt[NN];
__device__ int   d_off[NN + 1];
__device__ int   d_cur[NN];
__device__ int   d_csr[EE];
__device__ int   d_flag[NN];    // frontier: hosts ∪ in-neighbors of hosts
__device__ int   d_ishost[NN];
__device__ int   d_list[NN];    // compacted frontier list
__device__ int   d_nf;          // frontier count
__device__ float d_dinv[NN];
__device__ float d_xw[(size_t)NN * H1];    // dinv * (x @ W1)
__device__ float d_x1[(size_t)NN * H1];    // relu(agg1 + b1) on frontier rows
__device__ float d_xw2[(size_t)NN * H2];   // dinv * (x1 @ W2), frontier rows only
__device__ float d_x2h[(size_t)BB * NHOST * H2];
__device__ float d_g[(size_t)BB * H1];     // global state

// ---------------- zero ------------------------------------------------------
__global__ void k_zero() {
    int i = blockIdx.x * blockDim.x + threadIdx.x;
    if (i < NN) { d_cnt[i] = 0; d_flag[i] = 0; d_ishost[i] = 0; }
    if (i < BB * H1) d_g[i] = 0.f;
    if (i == 0) d_nf = 0;
}

// count in-degree; also mark host nodes
__global__ void k_count_mh(const int* __restrict__ dst, const int* __restrict__ hidx) {
    int e = blockIdx.x * blockDim.x + threadIdx.x;
    if (e < EE) atomicAdd(&d_cnt[dst[e]], 1);
    if (e < BB * NHOST) {
        int n = hidx[e];
        d_ishost[n] = 1;
        d_flag[n] = 1;
    }
}

// 1 block, 1024 threads, 50 items each (51200 = 1024*50)
__global__ void k_scan() {
    __shared__ int part[1024];
    int t = threadIdx.x;
    int base = t * 50;
    int s = 0;
    for (int i = 0; i < 50; i++) s += d_cnt[base + i];
    part[t] = s;
    __syncthreads();
    for (int d = 1; d < 1024; d <<= 1) {
        int v = part[t];
        int add = (t >= d) ? part[t - d] : 0;
        __syncthreads();
        part[t] = v + add;
        __syncthreads();
    }
    int run = part[t] - s;  // exclusive prefix
    for (int i = 0; i < 50; i++) {
        int c = d_cnt[base + i];
        d_off[base + i] = run;
        d_cur[base + i] = run;
        d_dinv[base + i] = rsqrtf((float)(c + 1));  // +1 self loop
        run += c;
    }
    if (t == 1023) d_off[NN] = run;
}

// fill CSR; also mark in-neighbors of hosts (frontier)
__global__ void k_fill_me(const int* __restrict__ src, const int* __restrict__ dst) {
    int e = blockIdx.x * blockDim.x + threadIdx.x;
    if (e < EE) {
        int d = dst[e];
        int s = src[e];
        int p = atomicAdd(&d_cur[d], 1);
        d_csr[p] = s;
        if (d_ishost[d]) d_flag[s] = 1;
    }
}

// compact frontier flags into a list (order irrelevant: max + row-GEMM are
// order-independent per row → result deterministic)
__global__ void k_mklist() {
    int i = blockIdx.x * blockDim.x + threadIdx.x;
    if (i < NN && d_flag[i]) {
        int p = atomicAdd(&d_nf, 1);
        d_list[p] = i;
    }
}

// ---------------- GEMM1: xw = dinv * (x @ W1)  [51200,64]x[64,256] ---------
#define G1R 32
__global__ void k_gemm1(const float* __restrict__ x, const float* __restrict__ W1) {
    __shared__ float xs[IN_F][G1R + 2];
    int r0 = blockIdx.x * G1R;
    int t = threadIdx.x; // 256
    for (int i = t; i < G1R * IN_F; i += 256) {
        int r = i >> 6, k = i & 63;
        xs[k][r] = x[(size_t)(r0 + r) * IN_F + k];
    }
    __syncthreads();
    u64 acc[G1R / 2];
#pragma unroll
    for (int p = 0; p < G1R / 2; p++) acc[p] = 0ull;
    for (int k = 0; k < IN_F; k++) {
        float w = __ldg(&W1[k * H1 + t]);
        u64 ww;
        asm("mov.b64 %0, {%1, %1};" : "=l"(ww) : "f"(w));
#pragma unroll
        for (int p = 0; p < G1R / 2; p++) {
            u64 xv = *reinterpret_cast<const u64*>(&xs[k][2 * p]);
            asm("fma.rn.f32x2 %0, %1, %2, %0;" : "+l"(acc[p]) : "l"(xv), "l"(ww));
        }
    }
#pragma unroll
    for (int p = 0; p < G1R / 2; p++) {
        float lo, hi;
        asm("mov.b64 {%0, %1}, %2;" : "=f"(lo), "=f"(hi) : "l"(acc[p]));
        d_xw[(size_t)(r0 + 2 * p) * H1 + t]     = d_dinv[r0 + 2 * p] * lo;
        d_xw[(size_t)(r0 + 2 * p + 1) * H1 + t] = d_dinv[r0 + 2 * p + 1] * hi;
    }
}

// ---------------- layer-1 max aggregation (frontier list, r3 structure) ----
__global__ void k_agg1(const float* __restrict__ b1) {
    int bi = blockIdx.x;
    if (bi >= d_nf) return;
    int i = d_list[bi];
    int t = threadIdx.x; // 256
    __shared__ int nbr[256];
    float m = d_xw[(size_t)i * H1 + t];   // self message (y = dinv*xw)
    int e0 = d_off[i], e1 = d_off[i + 1];
    for (int base = e0; base < e1; base += 256) {
        int n = min(256, e1 - base);
        __syncthreads();
        if (t < n) nbr[t] = d_csr[base + t];
        __syncthreads();
        int e = 0;
        for (; e + 4 <= n; e += 4) {
            int s0 = nbr[e], s1 = nbr[e + 1], s2 = nbr[e + 2], s3 = nbr[e + 3];
            float v0 = __ldg(&d_xw[(size_t)s0 * H1 + t]);
            float v1 = __ldg(&d_xw[(size_t)s1 * H1 + t]);
            float v2 = __ldg(&d_xw[(size_t)s2 * H1 + t]);
            float v3 = __ldg(&d_xw[(size_t)s3 * H1 + t]);
            m = fmaxf(m, fmaxf(fmaxf(v0, v1), fmaxf(v2, v3)));
        }
        for (; e < n; e++)
            m = fmaxf(m, __ldg(&d_xw[(size_t)nbr[e] * H1 + t]));
    }
    d_x1[(size_t)i * H1 + t] = fmaxf(d_dinv[i] * m + b1[t], 0.f);
}

// ---------------- GEMM2 on frontier rows: xw2 = dinv * (x1 @ W2) -----------
#define G2R 64
__global__ void k_gemm2(const float* __restrict__ W2) {
    int r0 = blockIdx.x * G2R;
    int nf = d_nf;
    if (r0 >= nf) return;
    __shared__ float xs[64][G2R + 2];
    __shared__ int rows[G2R];
    int t = threadIdx.x;      // 256
    int j = t & 63;
    int rg = t >> 6;
    if (t < G2R) rows[t] = d_list[min(r0 + t, nf - 1)];  // tail clamps (dup rows benign)
    __syncthreads();
    u64 acc[8];
#pragma unroll
    for (int p = 0; p < 8; p++) acc[p] = 0ull;
    for (int kc = 0; kc < H1; kc += 64) {
        __syncthreads();
        for (int i = t; i < G2R * 64; i += 256) {
            int r = i >> 6, k = i & 63;
            xs[k][r] = d_x1[(size_t)rows[r] * H1 + kc + k];
        }
        __syncthreads();
        for (int k = 0; k < 64; k++) {
            float w = __ldg(&W2[(kc + k) * H2 + j]);
            u64 ww;
            asm("mov.b64 %0, {%1, %1};" : "=l"(ww) : "f"(w));
#pragma unroll
            for (int p = 0; p < 8; p++) {
                u64 xv = *reinterpret_cast<const u64*>(&xs[k][rg * 16 + 2 * p]);
                asm("fma.rn.f32x2 %0, %1, %2, %0;" : "+l"(acc[p]) : "l"(xv), "l"(ww));
            }
        }
    }
#pragma unroll
    for (int p = 0; p < 8; p++) {
        float lo, hi;
        asm("mov.b64 {%0, %1}, %2;" : "=f"(lo), "=f"(hi) : "l"(acc[p]));
        int rl = rg * 16 + 2 * p;
        int ga = rows[rl], gb2 = rows[rl + 1];
        d_xw2[(size_t)ga * H2 + j]  = d_dinv[ga] * lo;
        d_xw2[(size_t)gb2 * H2 + j] = d_dinv[gb2] * hi;
    }
}

// ---------------- layer-2 max aggregation (HOST nodes only) ---------------
__global__ void k_agg2(const int* __restrict__ hidx, const float* __restrict__ b2) {
    int hi = blockIdx.x;       // 0..BB*NHOST-1
    int t = threadIdx.x;       // 64
    __shared__ int nbr[64];
    int node = hidx[hi];
    float m = d_xw2[(size_t)node * H2 + t];
    int e0 = d_off[node], e1 = d_off[node + 1];
    for (int base = e0; base < e1; base += 64) {
        int n = min(64, e1 - base);
        __syncthreads();
        if (t < n) nbr[t] = d_csr[base + t];
        __syncthreads();
        int e = 0;
        for (; e + 4 <= n; e += 4) {
            int s0 = nbr[e], s1 = nbr[e + 1], s2 = nbr[e + 2], s3 = nbr[e + 3];
            float v0 = __ldg(&d_xw2[(size_t)s0 * H2 + t]);
            float v1 = __ldg(&d_xw2[(size_t)s1 * H2 + t]);
            float v2 = __ldg(&d_xw2[(size_t)s2 * H2 + t]);
            float v3 = __ldg(&d_xw2[(size_t)s3 * H2 + t]);
            m = fmaxf(m, fmaxf(fmaxf(v0, v1), fmaxf(v2, v3)));
        }
        for (; e < n; e++)
            m = fmaxf(m, __ldg(&d_xw2[(size_t)nbr[e] * H2 + t]));
    }
    d_x2h[(size_t)hi * H2 + t] = fmaxf(d_dinv[node] * m + b2[t], 0.f);
}

// ---------------- self attention (r3 form; templated on F,H) --------------
template <int F, int H>
__global__ void k_attn(const float* __restrict__ v, const int* __restrict__ hidx,
                       const float* __restrict__ aW, const float* __restrict__ ab,
                       const float* __restrict__ fW, const float* __restrict__ fb,
                       const float* __restrict__ gW, const float* __restrict__ gb) {
    int b = blockIdx.x;
    int t = threadIdx.x; // 256
    __shared__ float vs[NHOST * F];
    __shared__ float ls[NHOST * H];
    __shared__ float mx[NHOST], sm[NHOST];
    __shared__ float outs[H];
    __shared__ float gs[H1];

    for (int i = t; i < NHOST * F; i += 256) {
        int h = i / F, f = i % F;
        int row = hidx ? hidx[b * NHOST + h] : (b * NHOST + h);
        vs[i] = v[(size_t)row * F + f];
    }
    gs[t] = d_g[(size_t)b * H1 + t];
    __syncthreads();

    float aL[NHOST], fV[NHOST];
    if (t < H) {
#pragma unroll
        for (int h = 0; h < NHOST; h++) { aL[h] = ab[t]; fV[h] = fb[t]; }
        for (int f = 0; f < F; f++) {
            float wa = __ldg(&aW[f * H + t]);
            float wf = __ldg(&fW[f * H + t]);
#pragma unroll
            for (int h = 0; h < NHOST; h++) {
                float x = vs[h * F + f];
                aL[h] += x * wa;
                fV[h] += x * wf;
            }
        }
#pragma unroll
        for (int h = 0; h < NHOST; h++) ls[h * H + t] = aL[h];
    }
    __syncthreads();
    if (t < NHOST) {
        float m = -1e30f;
        for (int j = 0; j < H; j++) m = fmaxf(m, ls[t * H + j]);
        mx[t] = m;
    }
    __syncthreads();
    if (t < H) {
#pragma unroll
        for (int h = 0; h < NHOST; h++) ls[h * H + t] = expf(aL[h] - mx[h]);
    }
    __syncthreads();
    if (t < NHOST) {
        float s = 0.f;
        for (int j = 0; j < H; j++) s += ls[t * H + j];
        sm[t] = s;
    }
    __syncthreads();
    if (t < H) {
        float o = 0.f;
#pragma unroll
        for (int h = 0; h < NHOST; h++) o += (ls[h * H + t] / sm[h]) * fV[h];
        outs[t] = o;
    }
    __syncthreads();

    // g_new = concat(out[H], g[256]) @ gW[(H+256),256] + gb ; g += g_new
    float acc = gb[t];
    for (int k = 0; k < H; k++) acc += outs[k] * __ldg(&gW[k * H1 + t]);
    for (int k = 0; k < H1; k++) acc += gs[k] * __ldg(&gW[(H + k) * H1 + t]);
    d_g[(size_t)b * H1 + t] = gs[t] + acc;
}

// ---------------- final head: relu(g@o1W+o1b)@o2W + o2b -------------------
__global__ void k_head(const float* __restrict__ o1W, const float* __restrict__ o1b,
                       const float* __restrict__ o2W, const float* __restrict__ o2b,
                       float* __restrict__ out) {
    int b = blockIdx.x;
    int t = threadIdx.x; // 64
    __shared__ float gs[H1];
    for (int i = t; i < H1; i += 64) gs[i] = d_g[(size_t)b * H1 + i];
    __syncthreads();
    float acc = o1b[t];
    for (int k = 0; k < H1; k++) acc += gs[k] * __ldg(&o1W[k * H2 + t]);
    float v = fmaxf(acc, 0.f) * __ldg(&o2W[t]);
    __shared__ float rs[64];
    rs[t] = v;
    __syncthreads();
    if (t < 32) {
        float s = rs[t] + rs[t + 32];
#pragma unroll
        for (int d = 16; d > 0; d >>= 1) s += __shfl_down_sync(0xffffffffu, s, d);
        if (t == 0) out[b] = s + o2b[0];
    }
}

// ---------------- launch ---------------------------------------------------
extern "C" void kernel_launch(void* const* d_in, const int* in_sizes, int n_in,
                              void* d_out, int out_size) {
    const float* x       = (const float*)d_in[0];
    const int*   ei      = (const int*)d_in[1];   // [2,E] int32
    const int*   hostidx = (const int*)d_in[2];
    const float* W1 = (const float*)d_in[3];
    const float* b1 = (const float*)d_in[4];
    const float* W2 = (const float*)d_in[5];
    const float* b2 = (const float*)d_in[6];
    const float* a0W = (const float*)d_in[7];  const float* a0b = (const float*)d_in[8];
    const float* f0W = (const float*)d_in[9];  const float* f0b = (const float*)d_in[10];
    const float* g0W = (const float*)d_in[11]; const float* g0b = (const float*)d_in[12];
    const float* a1W = (const float*)d_in[13]; const float* a1b = (const float*)d_in[14];
    const float* f1W = (const float*)d_in[15]; const float* f1b = (const float*)d_in[16];
    const float* g1W = (const float*)d_in[17]; const float* g1b = (const float*)d_in[18];
    const float* a2W = (const float*)d_in[19]; const float* a2b = (const float*)d_in[20];
    const float* f2W = (const float*)d_in[21]; const float* f2b = (const float*)d_in[22];
    const float* g2W = (const float*)d_in[23]; const float* g2b = (const float*)d_in[24];
    const float* o1W = (const float*)d_in[25]; const float* o1b = (const float*)d_in[26];
    const float* o2W = (const float*)d_in[27]; const float* o2b = (const float*)d_in[28];
    float* out = (float*)d_out;

    const int* src = ei;
    const int* dst = ei + EE;

    float* x1_ptr;  cudaGetSymbolAddress((void**)&x1_ptr,  d_x1);
    float* x2h_ptr; cudaGetSymbolAddress((void**)&x2h_ptr, d_x2h);

    k_zero<<<ZN / 256, 256>>>();                               // 1
    k_count_mh<<<(EE + 255) / 256, 256>>>(dst, hostidx);       // 2
    k_scan<<<1, 1024>>>();                                     // 3
    k_gemm1<<<NN / G1R, 256>>>(x, W1);                         // 4  ← profiled slot
    k_fill_me<<<(EE + 255) / 256, 256>>>(src, dst);            // 5
    k_mklist<<<NN / 256, 256>>>();                             // 6

    // stage 0 attention (only needs d_g=0 and x)
    k_attn<IN_F, H1><<<BB, 256>>>(x, hostidx, a0W, a0b, f0W, f0b, g0W, g0b);    // 7

    // layer 1
    k_agg1<<<NN, 256>>>(b1);                                   // 8 (blocks > nf exit)
    k_attn<H1, H1><<<BB, 256>>>(x1_ptr, hostidx, a1W, a1b, f1W, f1b, g1W, g1b); // 9

    // layer 2 (GEMM + aggregation on frontier/host rows only)
    k_gemm2<<<NN / G2R, 256>>>(W2);                            // 10 (blocks > nf exit)
    k_agg2<<<BB * NHOST, 64>>>(hostidx, b2);                   // 11
    k_attn<H2, H2><<<BB, 256>>>(x2h_ptr, (const int*)nullptr, a2W, a2b, f2W, f2b, g2W, g2b); // 12

    // head
    k_head<<<BB, 64>>>(o1W, o1b, o2W, o2b, out);               // 13
}

// round 6
// speedup vs baseline: 1.2754x; 1.0103x over previous
#include <cuda_runtime.h>
#include <math.h>

#define NN 51200      // nodes
#define EE 409600     // edges (without self loops)
#define BB 256        // batch
#define NHOST 13
#define IN_F 64
#define H1 256
#define H2 64
#define ZN 65536      // max(NN, BB*H1) — elements to zero

typedef unsigned long long u64;

// ---------------- scratch (static device globals; no runtime alloc) -------
__device__ int   d_cnt[NN];
__device__ int   d_off[NN + 1];
__device__ int   d_cur[NN];
__device__ int   d_csr[EE];
__device__ int   d_flag[NN];    // frontier: hosts ∪ in-neighbors of hosts
__device__ int   d_ishost[NN];
__device__ int   d_list[NN];    // compacted frontier list
__device__ int   d_nf;          // frontier count
__device__ float d_dinv[NN];
__device__ float d_xw[(size_t)NN * H1];    // dinv * (x @ W1)
__device__ float d_x1[(size_t)NN * H1];    // relu(agg1 + b1) on frontier rows
__device__ float d_xw2[(size_t)NN * H2];   // dinv * (x1 @ W2), frontier rows only
__device__ float d_x2h[(size_t)BB * NHOST * H2];
__device__ float d_g[(size_t)BB * H1];     // global state

// ---------------- zero ------------------------------------------------------
__global__ void k_zero() {
    int i = blockIdx.x * blockDim.x + threadIdx.x;
    if (i < NN) { d_cnt[i] = 0; d_flag[i] = 0; d_ishost[i] = 0; }
    if (i < BB * H1) d_g[i] = 0.f;
    if (i == 0) d_nf = 0;
}

// count in-degree; also mark host nodes
__global__ void k_count_mh(const int* __restrict__ dst, const int* __restrict__ hidx) {
    int e = blockIdx.x * blockDim.x + threadIdx.x;
    if (e < EE) atomicAdd(&d_cnt[dst[e]], 1);
    if (e < BB * NHOST) {
        int n = hidx[e];
        d_ishost[n] = 1;
        d_flag[n] = 1;
    }
}

// 1 block, 1024 threads, 50 items each (51200 = 1024*50)
__global__ void k_scan() {
    __shared__ int part[1024];
    int t = threadIdx.x;
    int base = t * 50;
    int s = 0;
    for (int i = 0; i < 50; i++) s += d_cnt[base + i];
    part[t] = s;
    __syncthreads();
    for (int d = 1; d < 1024; d <<= 1) {
        int v = part[t];
        int add = (t >= d) ? part[t - d] : 0;
        __syncthreads();
        part[t] = v + add;
        __syncthreads();
    }
    int run = part[t] - s;  // exclusive prefix
    for (int i = 0; i < 50; i++) {
        int c = d_cnt[base + i];
        d_off[base + i] = run;
        d_cur[base + i] = run;
        d_dinv[base + i] = rsqrtf((float)(c + 1));  // +1 self loop
        run += c;
    }
    if (t == 1023) d_off[NN] = run;
}

// fill CSR; also mark in-neighbors of hosts (frontier)
__global__ void k_fill_me(const int* __restrict__ src, const int* __restrict__ dst) {
    int e = blockIdx.x * blockDim.x + threadIdx.x;
    if (e < EE) {
        int d = dst[e];
        int s = src[e];
        int p = atomicAdd(&d_cur[d], 1);
        d_csr[p] = s;
        if (d_ishost[d]) d_flag[s] = 1;
    }
}

// compact frontier flags into a list (order irrelevant: max + row-GEMM are
// order-independent per row → result deterministic)
__global__ void k_mklist() {
    int i = blockIdx.x * blockDim.x + threadIdx.x;
    if (i < NN && d_flag[i]) {
        int p = atomicAdd(&d_nf, 1);
        d_list[p] = i;
    }
}

// ---------------- GEMM1: xw = dinv * (x @ W1)  [51200,64]x[64,256] ---------
// Block tile: 32 rows x 256 cols. Thread (rg=t>>6, cg=t&63): 8 rows x 4 cols.
// Per k: 4 LDS.64 (row pairs) + 1 LDG.128 (w) + 16 FFMA2.
#define G1R 32
__global__ void k_gemm1(const float* __restrict__ x, const float* __restrict__ W1) {
    __shared__ float xs[IN_F][G1R + 2];   // [k][r], +2 keeps rows 8B aligned
    int r0 = blockIdx.x * G1R;
    int t = threadIdx.x; // 256
    int rg = t >> 6;     // 0..3 → rows rg*8 .. rg*8+7
    int cg = t & 63;     // cols cg*4 .. cg*4+3
    for (int i = t; i < G1R * IN_F; i += 256) {
        int r = i >> 6, k = i & 63;
        xs[k][r] = x[(size_t)(r0 + r) * IN_F + k];
    }
    __syncthreads();
    u64 acc[4][4];       // [row pair p][col c]
#pragma unroll
    for (int p = 0; p < 4; p++)
#pragma unroll
        for (int c = 0; c < 4; c++) acc[p][c] = 0ull;
    for (int k = 0; k < IN_F; k++) {
        float4 w4 = *reinterpret_cast<const float4*>(&W1[k * H1 + cg * 4]);
        u64 wd[4];
        asm("mov.b64 %0, {%1, %1};" : "=l"(wd[0]) : "f"(w4.x));
        asm("mov.b64 %0, {%1, %1};" : "=l"(wd[1]) : "f"(w4.y));
        asm("mov.b64 %0, {%1, %1};" : "=l"(wd[2]) : "f"(w4.z));
        asm("mov.b64 %0, {%1, %1};" : "=l"(wd[3]) : "f"(w4.w));
        u64 xp[4];
#pragma unroll
        for (int p = 0; p < 4; p++)
            xp[p] = *reinterpret_cast<const u64*>(&xs[k][rg * 8 + 2 * p]);
#pragma unroll
        for (int p = 0; p < 4; p++)
#pragma unroll
            for (int c = 0; c < 4; c++)
                asm("fma.rn.f32x2 %0, %1, %2, %0;" : "+l"(acc[p][c]) : "l"(xp[p]), "l"(wd[c]));
    }
#pragma unroll
    for (int p = 0; p < 4; p++) {
        float lo[4], hi[4];
#pragma unroll
        for (int c = 0; c < 4; c++)
            asm("mov.b64 {%0, %1}, %2;" : "=f"(lo[c]), "=f"(hi[c]) : "l"(acc[p][c]));
        int ra = r0 + rg * 8 + 2 * p;
        float da = d_dinv[ra], db = d_dinv[ra + 1];
        float4 oa = make_float4(da * lo[0], da * lo[1], da * lo[2], da * lo[3]);
        float4 ob = make_float4(db * hi[0], db * hi[1], db * hi[2], db * hi[3]);
        *reinterpret_cast<float4*>(&d_xw[(size_t)ra * H1 + cg * 4])       = oa;
        *reinterpret_cast<float4*>(&d_xw[(size_t)(ra + 1) * H1 + cg * 4]) = ob;
    }
}

// ---------------- layer-1 max aggregation (frontier list) ------------------
__global__ void k_agg1(const float* __restrict__ b1) {
    int bi = blockIdx.x;
    if (bi >= d_nf) return;
    int i = d_list[bi];
    int t = threadIdx.x; // 256
    __shared__ int nbr[256];
    float m = d_xw[(size_t)i * H1 + t];   // self message (y = dinv*xw)
    int e0 = d_off[i], e1 = d_off[i + 1];
    for (int base = e0; base < e1; base += 256) {
        int n = min(256, e1 - base);
        __syncthreads();
        if (t < n) nbr[t] = d_csr[base + t];
        __syncthreads();
        int e = 0;
        for (; e + 4 <= n; e += 4) {
            int s0 = nbr[e], s1 = nbr[e + 1], s2 = nbr[e + 2], s3 = nbr[e + 3];
            float v0 = __ldg(&d_xw[(size_t)s0 * H1 + t]);
            float v1 = __ldg(&d_xw[(size_t)s1 * H1 + t]);
            float v2 = __ldg(&d_xw[(size_t)s2 * H1 + t]);
            float v3 = __ldg(&d_xw[(size_t)s3 * H1 + t]);
            m = fmaxf(m, fmaxf(fmaxf(v0, v1), fmaxf(v2, v3)));
        }
        for (; e < n; e++)
            m = fmaxf(m, __ldg(&d_xw[(size_t)nbr[e] * H1 + t]));
    }
    d_x1[(size_t)i * H1 + t] = fmaxf(d_dinv[i] * m + b1[t], 0.f);
}

// ---------------- GEMM2 on frontier rows: xw2 = dinv * (x1 @ W2) -----------
// Block tile: 128 frontier rows x 64 cols. Thread (rg=t>>4: 8 rows, cg=t&15: 4 cols).
#define G2R 128
__global__ void k_gemm2(const float* __restrict__ W2) {
    int r0 = blockIdx.x * G2R;
    int nf = d_nf;
    if (r0 >= nf) return;
    __shared__ float xs[64][G2R + 2];   // one 64-k chunk, [k][r]
    __shared__ int rows[G2R];
    int t = threadIdx.x;      // 256
    int rg = t >> 4;          // 0..15 → rows rg*8..+7
    int cg = t & 15;          // cols cg*4..+3
    if (t < G2R) rows[t] = d_list[min(r0 + t, nf - 1)];  // tail clamps (dup rows benign)
    __syncthreads();
    u64 acc[4][4];
#pragma unroll
    for (int p = 0; p < 4; p++)
#pragma unroll
        for (int c = 0; c < 4; c++) acc[p][c] = 0ull;
    for (int kc = 0; kc < H1; kc += 64) {
        __syncthreads();
        for (int i = t; i < G2R * 64; i += 256) {
            int r = i >> 6, k = i & 63;
            xs[k][r] = d_x1[(size_t)rows[r] * H1 + kc + k];
        }
        __syncthreads();
        for (int k = 0; k < 64; k++) {
            float4 w4 = *reinterpret_cast<const float4*>(&W2[(kc + k) * H2 + cg * 4]);
            u64 wd[4];
            asm("mov.b64 %0, {%1, %1};" : "=l"(wd[0]) : "f"(w4.x));
            asm("mov.b64 %0, {%1, %1};" : "=l"(wd[1]) : "f"(w4.y));
            asm("mov.b64 %0, {%1, %1};" : "=l"(wd[2]) : "f"(w4.z));
            asm("mov.b64 %0, {%1, %1};" : "=l"(wd[3]) : "f"(w4.w));
            u64 xp[4];
#pragma unroll
            for (int p = 0; p < 4; p++)
                xp[p] = *reinterpret_cast<const u64*>(&xs[k][rg * 8 + 2 * p]);
#pragma unroll
            for (int p = 0; p < 4; p++)
#pragma unroll
                for (int c = 0; c < 4; c++)
                    asm("fma.rn.f32x2 %0, %1, %2, %0;" : "+l"(acc[p][c]) : "l"(xp[p]), "l"(wd[c]));
        }
    }
#pragma unroll
    for (int p = 0; p < 4; p++) {
        float lo[4], hi[4];
#pragma unroll
        for (int c = 0; c < 4; c++)
            asm("mov.b64 {%0, %1}, %2;" : "=f"(lo[c]), "=f"(hi[c]) : "l"(acc[p][c]));
        int rla = rg * 8 + 2 * p;
        int ga = rows[rla], gb2 = rows[rla + 1];
        float da = d_dinv[ga], db = d_dinv[gb2];
        float4 oa = make_float4(da * lo[0], da * lo[1], da * lo[2], da * lo[3]);
        float4 ob = make_float4(db * hi[0], db * hi[1], db * hi[2], db * hi[3]);
        *reinterpret_cast<float4*>(&d_xw2[(size_t)ga * H2 + cg * 4])  = oa;
        *reinterpret_cast<float4*>(&d_xw2[(size_t)gb2 * H2 + cg * 4]) = ob;
    }
}

// ---------------- layer-2 max aggregation (HOST nodes only) ---------------
__global__ void k_agg2(const int* __restrict__ hidx, const float* __restrict__ b2) {
    int hi = blockIdx.x;       // 0..BB*NHOST-1
    int t = threadIdx.x;       // 64
    __shared__ int nbr[64];
    int node = hidx[hi];
    float m = d_xw2[(size_t)node * H2 + t];
    int e0 = d_off[node], e1 = d_off[node + 1];
    for (int base = e0; base < e1; base += 64) {
        int n = min(64, e1 - base);
        __syncthreads();
        if (t < n) nbr[t] = d_csr[base + t];
        __syncthreads();
        int e = 0;
        for (; e + 4 <= n; e += 4) {
            int s0 = nbr[e], s1 = nbr[e + 1], s2 = nbr[e + 2], s3 = nbr[e + 3];
            float v0 = __ldg(&d_xw2[(size_t)s0 * H2 + t]);
            float v1 = __ldg(&d_xw2[(size_t)s1 * H2 + t]);
            float v2 = __ldg(&d_xw2[(size_t)s2 * H2 + t]);
            float v3 = __ldg(&d_xw2[(size_t)s3 * H2 + t]);
            m = fmaxf(m, fmaxf(fmaxf(v0, v1), fmaxf(v2, v3)));
        }
        for (; e < n; e++)
            m = fmaxf(m, __ldg(&d_xw2[(size_t)nbr[e] * H2 + t]));
    }
    d_x2h[(size_t)hi * H2 + t] = fmaxf(d_dinv[node] * m + b2[t], 0.f);
}

// ---------------- self attention (r3 form; templated on F,H) --------------
template <int F, int H>
__global__ void k_attn(const float* __restrict__ v, const int* __restrict__ hidx,
                       const float* __restrict__ aW, const float* __restrict__ ab,
                       const float* __restrict__ fW, const float* __restrict__ fb,
                       const float* __restrict__ gW, const float* __restrict__ gb) {
    int b = blockIdx.x;
    int t = threadIdx.x; // 256
    __shared__ float vs[NHOST * F];
    __shared__ float ls[NHOST * H];
    __shared__ float mx[NHOST], sm[NHOST];
    __shared__ float outs[H];
    __shared__ float gs[H1];

    for (int i = t; i < NHOST * F; i += 256) {
        int h = i / F, f = i % F;
        int row = hidx ? hidx[b * NHOST + h] : (b * NHOST + h);
        vs[i] = v[(size_t)row * F + f];
    }
    gs[t] = d_g[(size_t)b * H1 + t];
    __syncthreads();

    float aL[NHOST], fV[NHOST];
    if (t < H) {
#pragma unroll
        for (int h = 0; h < NHOST; h++) { aL[h] = ab[t]; fV[h] = fb[t]; }
        for (int f = 0; f < F; f++) {
            float wa = __ldg(&aW[f * H + t]);
            float wf = __ldg(&fW[f * H + t]);
#pragma unroll
            for (int h = 0; h < NHOST; h++) {
                float x = vs[h * F + f];
                aL[h] += x * wa;
                fV[h] += x * wf;
            }
        }
#pragma unroll
        for (int h = 0; h < NHOST; h++) ls[h * H + t] = aL[h];
    }
    __syncthreads();
    if (t < NHOST) {
        float m = -1e30f;
        for (int j = 0; j < H; j++) m = fmaxf(m, ls[t * H + j]);
        mx[t] = m;
    }
    __syncthreads();
    if (t < H) {
#pragma unroll
        for (int h = 0; h < NHOST; h++) ls[h * H + t] = expf(aL[h] - mx[h]);
    }
    __syncthreads();
    if (t < NHOST) {
        float s = 0.f;
        for (int j = 0; j < H; j++) s += ls[t * H + j];
        sm[t] = s;
    }
    __syncthreads();
    if (t < H) {
        float o = 0.f;
#pragma unroll
        for (int h = 0; h < NHOST; h++) o += (ls[h * H + t] / sm[h]) * fV[h];
        outs[t] = o;
    }
    __syncthreads();

    // g_new = concat(out[H], g[256]) @ gW[(H+256),256] + gb ; g += g_new
    float acc = gb[t];
    for (int k = 0; k < H; k++) acc += outs[k] * __ldg(&gW[k * H1 + t]);
    for (int k = 0; k < H1; k++) acc += gs[k] * __ldg(&gW[(H + k) * H1 + t]);
    d_g[(size_t)b * H1 + t] = gs[t] + acc;
}

// ---------------- final head: relu(g@o1W+o1b)@o2W + o2b -------------------
__global__ void k_head(const float* __restrict__ o1W, const float* __restrict__ o1b,
                       const float* __restrict__ o2W, const float* __restrict__ o2b,
                       float* __restrict__ out) {
    int b = blockIdx.x;
    int t = threadIdx.x; // 64
    __shared__ float gs[H1];
    for (int i = t; i < H1; i += 64) gs[i] = d_g[(size_t)b * H1 + i];
    __syncthreads();
    float acc = o1b[t];
    for (int k = 0; k < H1; k++) acc += gs[k] * __ldg(&o1W[k * H2 + t]);
    float v = fmaxf(acc, 0.f) * __ldg(&o2W[t]);
    __shared__ float rs[64];
    rs[t] = v;
    __syncthreads();
    if (t < 32) {
        float s = rs[t] + rs[t + 32];
#pragma unroll
        for (int d = 16; d > 0; d >>= 1) s += __shfl_down_sync(0xffffffffu, s, d);
        if (t == 0) out[b] = s + o2b[0];
    }
}

// ---------------- launch ---------------------------------------------------
extern "C" void kernel_launch(void* const* d_in, const int* in_sizes, int n_in,
                              void* d_out, int out_size) {
    const float* x       = (const float*)d_in[0];
    const int*   ei      = (const int*)d_in[1];   // [2,E] int32
    const int*   hostidx = (const int*)d_in[2];
    const float* W1 = (const float*)d_in[3];
    const float* b1 = (const float*)d_in[4];
    const float* W2 = (const float*)d_in[5];
    const float* b2 = (const float*)d_in[6];
    const float* a0W = (const float*)d_in[7];  const float* a0b = (const float*)d_in[8];
    const float* f0W = (const float*)d_in[9];  const float* f0b = (const float*)d_in[10];
    const float* g0W = (const float*)d_in[11]; const float* g0b = (const float*)d_in[12];
    const float* a1W = (const float*)d_in[13]; const float* a1b = (const float*)d_in[14];
    const float* f1W = (const float*)d_in[15]; const float* f1b = (const float*)d_in[16];
    const float* g1W = (const float*)d_in[17]; const float* g1b = (const float*)d_in[18];
    const float* a2W = (const float*)d_in[19]; const float* a2b = (const float*)d_in[20];
    const float* f2W = (const float*)d_in[21]; const float* f2b = (const float*)d_in[22];
    const float* g2W = (const float*)d_in[23]; const float* g2b = (const float*)d_in[24];
    const float* o1W = (const float*)d_in[25]; const float* o1b = (const float*)d_in[26];
    const float* o2W = (const float*)d_in[27]; const float* o2b = (const float*)d_in[28];
    float* out = (float*)d_out;

    const int* src = ei;
    const int* dst = ei + EE;

    float* x1_ptr;  cudaGetSymbolAddress((void**)&x1_ptr,  d_x1);
    float* x2h_ptr; cudaGetSymbolAddress((void**)&x2h_ptr, d_x2h);

    k_zero<<<ZN / 256, 256>>>();                               // 1
    k_count_mh<<<(EE + 255) / 256, 256>>>(dst, hostidx);       // 2
    k_scan<<<1, 1024>>>();                                     // 3
    // stage 0 attention (only needs d_g=0 and x) — slot 4 → profiled
    k_attn<IN_F, H1><<<BB, 256>>>(x, hostidx, a0W, a0b, f0W, f0b, g0W, g0b);    // 4
    k_gemm1<<<NN / G1R, 256>>>(x, W1);                         // 5
    k_fill_me<<<(EE + 255) / 256, 256>>>(src, dst);            // 6
    k_mklist<<<NN / 256, 256>>>();                             // 7

    // layer 1
    k_agg1<<<NN, 256>>>(b1);                                   // 8 (blocks > nf exit)
    k_attn<H1, H1><<<BB, 256>>>(x1_ptr, hostidx, a1W, a1b, f1W, f1b, g1W, g1b); // 9

    // layer 2 (GEMM + aggregation on frontier/host rows only)
    k_gemm2<<<(NN + G2R - 1) / G2R, 256>>>(W2);                // 10 (blocks > nf exit)
    k_agg2<<<BB * NHOST, 64>>>(hostidx, b2);                   // 11
    k_attn<H2, H2><<<BB, 256>>>(x2h_ptr, (const int*)nullptr, a2W, a2b, f2W, f2b, g2W, g2b); // 12

    // head
    k_head<<<BB, 64>>>(o1W, o1b, o2W, o2b, out);               // 13
}